// round 2
// baseline (speedup 1.0000x reference)
#include <cuda_runtime.h>
#include <math.h>

#define BB 16
#define NN 1024
#define NHEADS 4
#define FIN 64
#define NHID 64
#define NCLASS 32
#define LRA 0.2f
#define FULL 0xffffffffu

// ---------------- scratch (device globals; no allocs) ----------------
__device__ __align__(16) float d_Wh1[NHEADS*BB*NN*NHID];   // 16.8 MB
__device__ float d_f1[NHEADS*BB*NN];
__device__ float d_g1[NHEADS*BB*NN];
__device__ float d_m1[NHEADS*BB*NN];
__device__ float d_is1[NHEADS*BB*NN];
__device__ __align__(16) float d_hcat[BB*NN*NHEADS*NHID];  // 16.8 MB
__device__ __align__(16) float d_Wh2[BB*NN*NCLASS];        // 2 MB
__device__ float d_f2[BB*NN];
__device__ float d_g2[BB*NN];
__device__ float d_m2[BB*NN];
__device__ float d_is2[BB*NN];
__device__ unsigned d_adjR[BB*NN*(NN/32)];   // [row][word]   2 MB
__device__ unsigned d_adjT[BB*(NN/32)*NN];   // [b][word][i]  2 MB

// ---------------- 1) pack adjacency to bitmasks ----------------
__global__ void pack_adj_kernel(const int* __restrict__ adj) {
    int warp = (blockIdx.x * blockDim.x + threadIdx.x) >> 5;
    int lane = threadIdx.x & 31;
    if (warp >= BB*NN) return;
    const int* row = adj + (long long)warp * NN;
    int b = warp >> 10, i = warp & 1023;
#pragma unroll
    for (int w = 0; w < 32; w++) {
        unsigned m = __ballot_sync(FULL, row[w*32 + lane] > 0);
        if (lane == 0) {
            d_adjR[warp*32 + w] = m;
            d_adjT[(b*32 + w)*NN + i] = m;
        }
    }
}

// ---------------- 2) Wh1 = x @ W_heads[h];  f,g ----------------
// grid (NN/64, BB, NHEADS), block 256
__global__ void whx1_kernel(const float* __restrict__ x,
                            const float* __restrict__ Wh,
                            const float* __restrict__ ah) {
    __shared__ __align__(16) float sW[FIN*NHID];   // [k][c] 16 KB
    __shared__ float sX[64][FIN+1];                // 16.6 KB (padded)
    __shared__ float sA[2*NHID];
    int h = blockIdx.z, b = blockIdx.y, i0 = blockIdx.x*64;
    int tid = threadIdx.x;

    const float4* Wsrc = (const float4*)(Wh + (long long)h*FIN*NHID);
    float4* Wdst = (float4*)sW;
    for (int idx = tid; idx < FIN*NHID/4; idx += 256) Wdst[idx] = Wsrc[idx];
    if (tid < 2*NHID) sA[tid] = ah[h*2*NHID + tid];
    for (int idx = tid; idx < 64*FIN/4; idx += 256) {
        int r = idx >> 4, c4 = idx & 15;
        float4 v = *(const float4*)(x + (long long)(b*NN + i0 + r)*FIN + c4*4);
        sX[r][c4*4+0]=v.x; sX[r][c4*4+1]=v.y; sX[r][c4*4+2]=v.z; sX[r][c4*4+3]=v.w;
    }
    __syncthreads();

    int r = tid >> 2, ct = tid & 3, c0 = ct*16;
    float acc[16];
#pragma unroll
    for (int c = 0; c < 16; c++) acc[c] = 0.f;
#pragma unroll 4
    for (int k = 0; k < FIN; k++) {
        float xv = sX[r][k];
#pragma unroll
        for (int c4 = 0; c4 < 4; c4++) {
            float4 w = *(const float4*)(&sW[k*NHID + c0 + c4*4]);
            acc[c4*4+0] += xv*w.x; acc[c4*4+1] += xv*w.y;
            acc[c4*4+2] += xv*w.z; acc[c4*4+3] += xv*w.w;
        }
    }
    long long base = ((long long)(h*BB + b)*NN + i0 + r)*NHID + c0;
#pragma unroll
    for (int c4 = 0; c4 < 4; c4++)
        *(float4*)(&d_Wh1[base + c4*4]) =
            make_float4(acc[c4*4], acc[c4*4+1], acc[c4*4+2], acc[c4*4+3]);

    float pf = 0.f, pg = 0.f;
#pragma unroll
    for (int c = 0; c < 16; c++) { pf += acc[c]*sA[c0+c]; pg += acc[c]*sA[NHID+c0+c]; }
    pf += __shfl_xor_sync(FULL, pf, 1); pg += __shfl_xor_sync(FULL, pg, 1);
    pf += __shfl_xor_sync(FULL, pf, 2); pg += __shfl_xor_sync(FULL, pg, 2);
    if (ct == 0) {
        d_f1[(h*BB+b)*NN + i0 + r] = pf;
        d_g1[(h*BB+b)*NN + i0 + r] = pg;
    }
}

// ---------------- 3) layer-1 softmax stats (4 heads fused) ----------------
// grid BB*NN/8, block 256 (8 warps = 8 rows)
__global__ void stats1_kernel() {
    __shared__ float sG[NHEADS][NN];  // 16 KB
    int tid = threadIdx.x;
    int warp = tid >> 5, lane = tid & 31;
    int rowg = blockIdx.x*8 + warp;
    int b = rowg >> 10, i = rowg & 1023;
    for (int idx = tid; idx < NHEADS*NN; idx += 256) {
        int hh = idx >> 10, j = idx & 1023;
        sG[hh][j] = d_g1[(hh*BB + b)*NN + j];
    }
    __syncthreads();
    unsigned word = d_adjR[rowg*32 + lane];
    float fh[NHEADS], mg[NHEADS], s[NHEADS];
#pragma unroll
    for (int hh = 0; hh < NHEADS; hh++) {
        fh[hh] = d_f1[(hh*BB+b)*NN + i]; mg[hh] = -1e30f; s[hh] = 0.f;
    }
#pragma unroll 4
    for (int w = 0; w < 32; w++) {
        unsigned ww = __shfl_sync(FULL, word, w);
        if ((ww >> lane) & 1u) {
#pragma unroll
            for (int hh = 0; hh < NHEADS; hh++)
                mg[hh] = fmaxf(mg[hh], sG[hh][w*32 + lane]);
        }
    }
#pragma unroll
    for (int off = 16; off > 0; off >>= 1)
#pragma unroll
        for (int hh = 0; hh < NHEADS; hh++)
            mg[hh] = fmaxf(mg[hh], __shfl_xor_sync(FULL, mg[hh], off));
    float m[NHEADS];
#pragma unroll
    for (int hh = 0; hh < NHEADS; hh++) {
        float xm = fh[hh] + mg[hh];
        m[hh] = xm > 0.f ? xm : LRA*xm;
    }
#pragma unroll 4
    for (int w = 0; w < 32; w++) {
        unsigned ww = __shfl_sync(FULL, word, w);
        if ((ww >> lane) & 1u) {
#pragma unroll
            for (int hh = 0; hh < NHEADS; hh++) {
                float xx = fh[hh] + sG[hh][w*32 + lane];
                float e = xx > 0.f ? xx : LRA*xx;
                s[hh] += __expf(e - m[hh]);
            }
        }
    }
#pragma unroll
    for (int off = 16; off > 0; off >>= 1)
#pragma unroll
        for (int hh = 0; hh < NHEADS; hh++)
            s[hh] += __shfl_xor_sync(FULL, s[hh], off);
    if (lane == 0) {
#pragma unroll
        for (int hh = 0; hh < NHEADS; hh++) {
            d_m1[(hh*BB+b)*NN + i]  = m[hh];
            d_is1[(hh*BB+b)*NN + i] = 1.0f / fmaxf(s[hh], 1e-30f);
        }
    }
}

// ---------------- 4) PV: out = softmax(E) @ Wh  (masked GEMM) ----------------
// grid (NN/128, BB, heads), block 128
template<int LAYER>
__global__ __launch_bounds__(128) void pv_kernel(float* __restrict__ dout) {
    constexpr int F  = (LAYER == 1) ? NHID : NCLASS;
    constexpr int CN = F / 8;
    __shared__ float sG[NN];                       // 4 KB
    __shared__ float sP[128][33];                  // 16.9 KB padded
    __shared__ __align__(16) float sV[32][F+4];    // 8.7 / 4.6 KB padded
    int b = blockIdx.y;
    int h = blockIdx.z;
    int i0 = blockIdx.x * 128;
    int tid = threadIdx.x;
    int hb = (LAYER == 1) ? (h*BB + b) : b;
    const float* fA  = (LAYER == 1) ? d_f1  : d_f2;
    const float* gA  = (LAYER == 1) ? d_g1  : d_g2;
    const float* mA  = (LAYER == 1) ? d_m1  : d_m2;
    const float* isA = (LAYER == 1) ? d_is1 : d_is2;
    const float* Wh  = (LAYER == 1) ? (d_Wh1 + (long long)hb*NN*F)
                                    : (d_Wh2 + (long long)b*NN*F);
    for (int idx = tid; idx < NN; idx += 128) sG[idx] = __ldg(&gA[(long long)hb*NN + idx]);
    float fv = fA[(long long)hb*NN + i0 + tid];
    float mv = mA[(long long)hb*NN + i0 + tid];

    int rt = tid & 15, ct = tid >> 4;
    int c0 = ct * CN;
    float acc[8][CN];
#pragma unroll
    for (int rr = 0; rr < 8; rr++)
#pragma unroll
        for (int cc = 0; cc < CN; cc++) acc[rr][cc] = 0.f;

    const unsigned* adjTp = d_adjT + (long long)b*32*NN + i0 + tid;

#pragma unroll 1
    for (int jc = 0; jc < 32; jc++) {
        __syncthreads();
        // P tile: thread t = row t, one adj word covers the 32-col chunk
        unsigned word = adjTp[jc*NN];
#pragma unroll
        for (int j = 0; j < 32; j++) {
            float p = 0.f;
            if ((word >> j) & 1u) {
                float xx = fv + sG[jc*32 + j];
                float e = xx > 0.f ? xx : LRA*xx;
                p = __expf(e - mv);
            }
            sP[tid][j] = p;
        }
        // V tile (coalesced float4)
#pragma unroll
        for (int q = 0; q < (32*F/4)/128; q++) {
            int idx = tid + 128*q;
            int vr = idx / (F/4), c4 = idx % (F/4);
            float4 v = *(const float4*)(Wh + (long long)(jc*32 + vr)*F + c4*4);
            sV[vr][c4*4+0]=v.x; sV[vr][c4*4+1]=v.y; sV[vr][c4*4+2]=v.z; sV[vr][c4*4+3]=v.w;
        }
        __syncthreads();
#pragma unroll 4
        for (int k = 0; k < 32; k++) {
            float pv[8];
#pragma unroll
            for (int rr = 0; rr < 8; rr++) pv[rr] = sP[rt + rr*16][k];
            float vv[CN];
#pragma unroll
            for (int cc = 0; cc < CN; cc += 4) {
                float4 v = *(const float4*)(&sV[k][c0 + cc]);
                vv[cc]=v.x; vv[cc+1]=v.y; vv[cc+2]=v.z; vv[cc+3]=v.w;
            }
#pragma unroll
            for (int rr = 0; rr < 8; rr++)
#pragma unroll
                for (int cc = 0; cc < CN; cc++)
                    acc[rr][cc] += pv[rr]*vv[cc];
        }
    }
    // epilogue: normalize (+ ELU & concat for layer 1)
#pragma unroll
    for (int rr = 0; rr < 8; rr++) {
        int rl = rt + rr*16;
        float isv = isA[(long long)hb*NN + i0 + rl];
        if (LAYER == 1) {
            long long obase = ((long long)(b*NN + i0 + rl))*(NHEADS*NHID) + h*NHID + c0;
#pragma unroll
            for (int cc = 0; cc < CN; cc++) {
                float v = acc[rr][cc]*isv;
                v = v > 0.f ? v : expm1f(v);
                d_hcat[obase + cc] = v;
            }
        } else {
            long long obase = ((long long)(b*NN + i0 + rl))*NCLASS + c0;
#pragma unroll
            for (int cc = 0; cc < CN; cc++)
                dout[obase + cc] = acc[rr][cc]*isv;
        }
    }
}

// ---------------- 5) Wh2 = hcat @ W_out;  f2,g2 ----------------
// grid BB*NN/32, block 128
__global__ void whx2_kernel(const float* __restrict__ Wo,
                            const float* __restrict__ ao) {
    __shared__ float sH[32][257];      // 32.9 KB padded
    __shared__ float sA[2*NCLASS];
    __shared__ float sRed[32][4][2];
    int r0 = blockIdx.x * 32;          // global row
    int tid = threadIdx.x;
    int r = tid & 31, ct = tid >> 5, c0 = ct*8;
    if (tid < 2*NCLASS) sA[tid] = ao[tid];
    for (int idx = tid; idx < 32*256/4; idx += 128) {
        int rr = idx >> 6, c4 = idx & 63;
        float4 v = *(const float4*)(&d_hcat[(long long)(r0+rr)*256 + c4*4]);
        sH[rr][c4*4+0]=v.x; sH[rr][c4*4+1]=v.y; sH[rr][c4*4+2]=v.z; sH[rr][c4*4+3]=v.w;
    }
    __syncthreads();
    float acc[8];
#pragma unroll
    for (int c = 0; c < 8; c++) acc[c] = 0.f;
#pragma unroll 4
    for (int k = 0; k < 256; k++) {
        float hv = sH[r][k];
        float4 w0 = __ldg((const float4*)(Wo + k*NCLASS + c0));
        float4 w1 = __ldg((const float4*)(Wo + k*NCLASS + c0 + 4));
        acc[0]+=hv*w0.x; acc[1]+=hv*w0.y; acc[2]+=hv*w0.z; acc[3]+=hv*w0.w;
        acc[4]+=hv*w1.x; acc[5]+=hv*w1.y; acc[6]+=hv*w1.z; acc[7]+=hv*w1.w;
    }
    long long base = (long long)(r0+r)*NCLASS + c0;
    *(float4*)(&d_Wh2[base])     = make_float4(acc[0],acc[1],acc[2],acc[3]);
    *(float4*)(&d_Wh2[base + 4]) = make_float4(acc[4],acc[5],acc[6],acc[7]);
    float pf = 0.f, pg = 0.f;
#pragma unroll
    for (int c = 0; c < 8; c++) { pf += acc[c]*sA[c0+c]; pg += acc[c]*sA[NCLASS+c0+c]; }
    sRed[r][ct][0] = pf; sRed[r][ct][1] = pg;
    __syncthreads();
    if (tid < 32) {
        float f = sRed[tid][0][0]+sRed[tid][1][0]+sRed[tid][2][0]+sRed[tid][3][0];
        float g = sRed[tid][0][1]+sRed[tid][1][1]+sRed[tid][2][1]+sRed[tid][3][1];
        d_f2[r0+tid] = f; d_g2[r0+tid] = g;
    }
}

// ---------------- 6) layer-2 softmax stats ----------------
__global__ void stats2_kernel() {
    __shared__ float sG[NN];
    int tid = threadIdx.x;
    int warp = tid >> 5, lane = tid & 31;
    int rowg = blockIdx.x*8 + warp;
    int b = rowg >> 10;
    for (int idx = tid; idx < NN; idx += 256) sG[idx] = d_g2[b*NN + idx];
    __syncthreads();
    unsigned word = d_adjR[rowg*32 + lane];
    float fv = d_f2[rowg];
    float mg = -1e30f;
#pragma unroll 4
    for (int w = 0; w < 32; w++) {
        unsigned ww = __shfl_sync(FULL, word, w);
        if ((ww >> lane) & 1u) mg = fmaxf(mg, sG[w*32 + lane]);
    }
#pragma unroll
    for (int off = 16; off > 0; off >>= 1)
        mg = fmaxf(mg, __shfl_xor_sync(FULL, mg, off));
    float xm = fv + mg;
    float m = xm > 0.f ? xm : LRA*xm;
    float s = 0.f;
#pragma unroll 4
    for (int w = 0; w < 32; w++) {
        unsigned ww = __shfl_sync(FULL, word, w);
        if ((ww >> lane) & 1u) {
            float xx = fv + sG[w*32 + lane];
            float e = xx > 0.f ? xx : LRA*xx;
            s += __expf(e - m);
        }
    }
#pragma unroll
    for (int off = 16; off > 0; off >>= 1)
        s += __shfl_xor_sync(FULL, s, off);
    if (lane == 0) { d_m2[rowg] = m; d_is2[rowg] = 1.0f/fmaxf(s, 1e-30f); }
}

// ---------------- launch ----------------
extern "C" void kernel_launch(void* const* d_in, const int* in_sizes, int n_in,
                              void* d_out, int out_size) {
    (void)in_sizes; (void)n_in; (void)out_size;
    const float* x       = (const float*)d_in[0];
    const int*   adj     = (const int*)  d_in[1];
    const float* W_heads = (const float*)d_in[2];
    const float* a_heads = (const float*)d_in[3];
    const float* W_out   = (const float*)d_in[4];
    const float* a_out   = (const float*)d_in[5];
    float* out = (float*)d_out;

    pack_adj_kernel<<<BB*NN/8, 256>>>(adj);
    whx1_kernel<<<dim3(NN/64, BB, NHEADS), 256>>>(x, W_heads, a_heads);
    stats1_kernel<<<BB*NN/8, 256>>>();
    pv_kernel<1><<<dim3(NN/128, BB, NHEADS), 128>>>(nullptr);
    whx2_kernel<<<BB*NN/32, 128>>>(W_out, a_out);
    stats2_kernel<<<BB*NN/8, 256>>>();
    pv_kernel<2><<<dim3(NN/128, BB, 1), 128>>>(out);
}

// round 5
// speedup vs baseline: 2.0516x; 2.0516x over previous
#include <cuda_runtime.h>
#include <math.h>
#include <stdint.h>

#define BB 16
#define NN 1024
#define NHEADS 4
#define FIN 64
#define NHID 64
#define NCLASS 32
#define LRA 0.2f
#define FULL 0xffffffffu

// ---------------- scratch (device globals; no allocs) ----------------
__device__ __align__(16) float d_Wh1T[NHEADS*BB*NHID*NN];  // [h,b][c][j] 16.8 MB (tf32-rounded)
__device__ float d_f1[NHEADS*BB*NN];
__device__ float d_g1[NHEADS*BB*NN];
__device__ float d_is1[NHEADS*BB*NN];
__device__ __align__(16) float4 d_gv1[NHEADS*BB*NN];       // (g, e^g, e^{0.2g}, 0)
__device__ __align__(8)  float2 d_eac1[NHEADS*BB*NN];      // (e^{f-m}, e^{0.2f-m})
__device__ __align__(16) float d_hcat[BB*NN*NHEADS*NHID];  // 16.8 MB
__device__ __align__(16) float d_Wh2T[BB*NCLASS*NN];       // [b][c][j] 2 MB (tf32-rounded)
__device__ float d_f2[BB*NN];
__device__ float d_g2[BB*NN];
__device__ float d_is2[BB*NN];
__device__ __align__(16) float4 d_gv2[BB*NN];
__device__ __align__(8)  float2 d_eac2[BB*NN];
__device__ unsigned d_adjR[BB*NN*(NN/32)];   // [row][word]   2 MB
__device__ unsigned d_adjT[BB*(NN/32)*NN];   // [b][word][i]  2 MB

__device__ __forceinline__ float to_tf32(float x) {
    uint32_t r; asm("cvt.rna.tf32.f32 %0, %1;" : "=r"(r) : "f"(x));
    return __uint_as_float(r);
}
__device__ __forceinline__ uint32_t to_tf32_u(float x) {
    uint32_t r; asm("cvt.rna.tf32.f32 %0, %1;" : "=r"(r) : "f"(x));
    return r;
}
__device__ __forceinline__ void mma_tf32_16x8x8(float* d, const uint32_t* a, const uint32_t* b) {
    asm volatile(
        "mma.sync.aligned.m16n8k8.row.col.f32.tf32.tf32.f32 "
        "{%0,%1,%2,%3}, {%4,%5,%6,%7}, {%8,%9}, {%0,%1,%2,%3};"
        : "+f"(d[0]), "+f"(d[1]), "+f"(d[2]), "+f"(d[3])
        : "r"(a[0]), "r"(a[1]), "r"(a[2]), "r"(a[3]), "r"(b[0]), "r"(b[1]));
}

// ---------------- 1) pack adjacency to bitmasks ----------------
__global__ void pack_adj_kernel(const int* __restrict__ adj) {
    int warp = (blockIdx.x * blockDim.x + threadIdx.x) >> 5;
    int lane = threadIdx.x & 31;
    if (warp >= BB*NN) return;
    const int* row = adj + (long long)warp * NN;
    int b = warp >> 10, i = warp & 1023;
#pragma unroll
    for (int w = 0; w < 32; w++) {
        unsigned m = __ballot_sync(FULL, row[w*32 + lane] > 0);
        if (lane == 0) {
            d_adjR[warp*32 + w] = m;
            d_adjT[(b*32 + w)*NN + i] = m;
        }
    }
}

// ---------------- 2) Wh1T = (x @ W_heads[h])^T;  f,g ----------------
// grid (NN/64, BB, NHEADS), block 256
__global__ void whx1_kernel(const float* __restrict__ x,
                            const float* __restrict__ Wh,
                            const float* __restrict__ ah) {
    __shared__ __align__(16) float sW[FIN*NHID];
    __shared__ float sX[64][FIN+1];
    __shared__ float sA[2*NHID];
    int h = blockIdx.z, b = blockIdx.y, i0 = blockIdx.x*64;
    int tid = threadIdx.x;

    const float4* Wsrc = (const float4*)(Wh + (long long)h*FIN*NHID);
    float4* Wdst = (float4*)sW;
    for (int idx = tid; idx < FIN*NHID/4; idx += 256) Wdst[idx] = Wsrc[idx];
    if (tid < 2*NHID) sA[tid] = ah[h*2*NHID + tid];
    for (int idx = tid; idx < 64*FIN/4; idx += 256) {
        int r = idx >> 4, c4 = idx & 15;
        float4 v = *(const float4*)(x + (long long)(b*NN + i0 + r)*FIN + c4*4);
        sX[r][c4*4+0]=v.x; sX[r][c4*4+1]=v.y; sX[r][c4*4+2]=v.z; sX[r][c4*4+3]=v.w;
    }
    __syncthreads();

    int r = tid >> 2, ct = tid & 3, c0 = ct*16;
    float acc[16];
#pragma unroll
    for (int c = 0; c < 16; c++) acc[c] = 0.f;
#pragma unroll 4
    for (int k = 0; k < FIN; k++) {
        float xv = sX[r][k];
#pragma unroll
        for (int c4 = 0; c4 < 4; c4++) {
            float4 w = *(const float4*)(&sW[k*NHID + c0 + c4*4]);
            acc[c4*4+0] += xv*w.x; acc[c4*4+1] += xv*w.y;
            acc[c4*4+2] += xv*w.z; acc[c4*4+3] += xv*w.w;
        }
    }
    float* WT = d_Wh1T + (long long)(h*BB + b)*NHID*NN;
#pragma unroll
    for (int c = 0; c < 16; c++)
        WT[(long long)(c0 + c)*NN + i0 + r] = to_tf32(acc[c]);

    float pf = 0.f, pg = 0.f;
#pragma unroll
    for (int c = 0; c < 16; c++) { pf += acc[c]*sA[c0+c]; pg += acc[c]*sA[NHID+c0+c]; }
    pf += __shfl_xor_sync(FULL, pf, 1); pg += __shfl_xor_sync(FULL, pg, 1);
    pf += __shfl_xor_sync(FULL, pf, 2); pg += __shfl_xor_sync(FULL, pg, 2);
    if (ct == 0) {
        d_f1[(h*BB+b)*NN + i0 + r] = pf;
        d_g1[(h*BB+b)*NN + i0 + r] = pg;
    }
}

// ---------------- 3) layer-1 softmax stats (4 heads fused) ----------------
__global__ void stats1_kernel() {
    __shared__ float sG[NHEADS][NN];
    int tid = threadIdx.x;
    int warp = tid >> 5, lane = tid & 31;
    int rowg = blockIdx.x*8 + warp;
    int b = rowg >> 10, i = rowg & 1023;
    for (int idx = tid; idx < NHEADS*NN; idx += 256) {
        int hh = idx >> 10, j = idx & 1023;
        sG[hh][j] = d_g1[(hh*BB + b)*NN + j];
    }
    __syncthreads();
    unsigned word = d_adjR[rowg*32 + lane];
    float fh[NHEADS], mg[NHEADS], s[NHEADS];
#pragma unroll
    for (int hh = 0; hh < NHEADS; hh++) {
        fh[hh] = d_f1[(hh*BB+b)*NN + i]; mg[hh] = -1e30f; s[hh] = 0.f;
    }
#pragma unroll 4
    for (int w = 0; w < 32; w++) {
        unsigned ww = __shfl_sync(FULL, word, w);
        if ((ww >> lane) & 1u) {
#pragma unroll
            for (int hh = 0; hh < NHEADS; hh++)
                mg[hh] = fmaxf(mg[hh], sG[hh][w*32 + lane]);
        }
    }
#pragma unroll
    for (int off = 16; off > 0; off >>= 1)
#pragma unroll
        for (int hh = 0; hh < NHEADS; hh++)
            mg[hh] = fmaxf(mg[hh], __shfl_xor_sync(FULL, mg[hh], off));
    float m[NHEADS];
#pragma unroll
    for (int hh = 0; hh < NHEADS; hh++) {
        float xm = fh[hh] + mg[hh];
        m[hh] = xm > 0.f ? xm : LRA*xm;
    }
#pragma unroll 4
    for (int w = 0; w < 32; w++) {
        unsigned ww = __shfl_sync(FULL, word, w);
        if ((ww >> lane) & 1u) {
#pragma unroll
            for (int hh = 0; hh < NHEADS; hh++) {
                float xx = fh[hh] + sG[hh][w*32 + lane];
                float e = xx > 0.f ? xx : LRA*xx;
                s[hh] += __expf(e - m[hh]);
            }
        }
    }
#pragma unroll
    for (int off = 16; off > 0; off >>= 1)
#pragma unroll
        for (int hh = 0; hh < NHEADS; hh++)
            s[hh] += __shfl_xor_sync(FULL, s[hh], off);
    if (lane == 0) {
#pragma unroll
        for (int hh = 0; hh < NHEADS; hh++) {
            int o = (hh*BB+b)*NN + i;
            d_is1[o] = 1.0f / fmaxf(s[hh], 1e-30f);
            d_eac1[o] = make_float2(__expf(fh[hh] - m[hh]), __expf(LRA*fh[hh] - m[hh]));
            float gg = sG[hh][i];
            d_gv1[o] = make_float4(gg, __expf(gg), __expf(LRA*gg), 0.f);
        }
    }
}

// ---------------- 4) PV via mma.sync tf32 (masked softmax x Wh) ----------------
// grid (NN/128, BB, heads), block 128 (4 warps; warp w = rows w*32..w*32+31)
template<int LAYER>
__global__ __launch_bounds__(128) void pv_mma_kernel(float* __restrict__ dout) {
    constexpr int F  = (LAYER == 1) ? NHID : NCLASS;
    constexpr int NT = F / 8;              // n-tiles of 8
    constexpr int NQ = F / 16;             // float4 B loads per thread per chunk
    __shared__ float4 sGv[NN];             // 16 KB (g, Eb, Ed)
    __shared__ float  sF[128];
    __shared__ float2 sEac[128];
    __shared__ float  sIs[128];
    __shared__ float  sBf[2][4][NT][32][2];  // fragment-shuffled B tiles

    const int tid = threadIdx.x, wid = tid >> 5, lane = tid & 31;
    const int g = lane >> 2, t = lane & 3;
    const int b = blockIdx.y, h = blockIdx.z, i0 = blockIdx.x * 128;
    const int hb = (LAYER == 1) ? (h*BB + b) : b;
    const float*  fA  = (LAYER == 1) ? d_f1  : d_f2;
    const float*  isA = (LAYER == 1) ? d_is1 : d_is2;
    const float2* eac = (LAYER == 1) ? d_eac1 : d_eac2;
    const float4* gvA = (LAYER == 1) ? d_gv1 : d_gv2;
    const float*  BT  = (LAYER == 1) ? (d_Wh1T + (long long)hb*F*NN)
                                     : (d_Wh2T + (long long)b*F*NN);

    for (int idx = tid; idx < NN; idx += 128) sGv[idx] = gvA[(long long)hb*NN + idx];
    sF[tid]   = fA[(long long)hb*NN + i0 + tid];
    sEac[tid] = eac[(long long)hb*NN + i0 + tid];
    sIs[tid]  = isA[(long long)hb*NN + i0 + tid];
    __syncthreads();

    // per-thread row registers (rows g, g+8, g+16, g+24 of this warp's stripe)
    float fr[4], ear[4], ecr[4];
#pragma unroll
    for (int r = 0; r < 4; r++) {
        int lr = wid*32 + g + 8*r;
        fr[r] = sF[lr]; ear[r] = sEac[lr].x; ecr[r] = sEac[lr].y;
    }

    float acc[2][NT][4];
#pragma unroll
    for (int mt = 0; mt < 2; mt++)
#pragma unroll
        for (int nt = 0; nt < NT; nt++)
#pragma unroll
            for (int c = 0; c < 4; c++) acc[mt][nt][c] = 0.f;

    const unsigned* adjTp = d_adjT + (long long)b*32*NN + i0 + tid;

    // prologue: prefetch chunk 0
    float4 breg[NQ];
#pragma unroll
    for (int q = 0; q < NQ; q++) {
        int idx = tid + 128*q; int n = idx >> 3, k4 = idx & 7;
        breg[q] = *(const float4*)(BT + (long long)n*NN + k4*4);
    }
    unsigned aw = adjTp[0];

#pragma unroll 1
    for (int chunk = 0; chunk < 32; chunk++) {
        const int buf = chunk & 1;
        // stage B fragments into smem
#pragma unroll
        for (int q = 0; q < NQ; q++) {
            int idx = tid + 128*q; int n = idx >> 3, k4 = idx & 7;
            int ks = k4 >> 1, bb = k4 & 1, nt = n >> 3, ln = (n & 7) * 4;
            sBf[buf][ks][nt][ln+0][bb] = breg[q].x;
            sBf[buf][ks][nt][ln+1][bb] = breg[q].y;
            sBf[buf][ks][nt][ln+2][bb] = breg[q].z;
            sBf[buf][ks][nt][ln+3][bb] = breg[q].w;
        }
        __syncthreads();

        // adj words for my 4 rows
        unsigned wr[4];
#pragma unroll
        for (int r = 0; r < 4; r++) wr[r] = __shfl_sync(FULL, aw, g + 8*r);

        // prefetch next chunk
        if (chunk < 31) {
#pragma unroll
            for (int q = 0; q < NQ; q++) {
                int idx = tid + 128*q; int n = idx >> 3, k4 = idx & 7;
                breg[q] = *(const float4*)(BT + (long long)n*NN + (chunk+1)*32 + k4*4);
            }
            aw = adjTp[(long long)(chunk+1)*NN];
        }

        // 4 k-steps of 8
#pragma unroll
        for (int s = 0; s < 4; s++) {
            const float4 gva = sGv[chunk*32 + 8*s + t];
            const float4 gvb = sGv[chunk*32 + 8*s + t + 4];
            uint32_t afr[2][4];
#pragma unroll
            for (int mt = 0; mt < 2; mt++) {
#pragma unroll
                for (int half = 0; half < 2; half++) {
                    int r = mt*2 + half;           // row g + 8*r
                    // kk = t + 8s (a0/a1) and t+4+8s (a2/a3)
                    float s0 = fr[r] + gva.x;
                    float p0 = (s0 > 0.f ? ear[r] : ecr[r]) * (s0 > 0.f ? gva.y : gva.z);
                    p0 = ((wr[r] >> (8*s + t)) & 1u) ? p0 : 0.f;
                    float s1 = fr[r] + gvb.x;
                    float p1 = (s1 > 0.f ? ear[r] : ecr[r]) * (s1 > 0.f ? gvb.y : gvb.z);
                    p1 = ((wr[r] >> (8*s + t + 4)) & 1u) ? p1 : 0.f;
                    afr[mt][half]     = to_tf32_u(p0);
                    afr[mt][half + 2] = to_tf32_u(p1);
                }
            }
#pragma unroll
            for (int nt = 0; nt < NT; nt++) {
                uint32_t bf[2];
                float2 bv = *(const float2*)&sBf[buf][s][nt][lane][0];
                bf[0] = __float_as_uint(bv.x); bf[1] = __float_as_uint(bv.y);
                mma_tf32_16x8x8(acc[0][nt], afr[0], bf);
                mma_tf32_16x8x8(acc[1][nt], afr[1], bf);
            }
        }
    }

    // epilogue: normalize (+ ELU & concat for layer 1)
#pragma unroll
    for (int mt = 0; mt < 2; mt++) {
#pragma unroll
        for (int half = 0; half < 2; half++) {
            int lrow = wid*32 + mt*16 + g + 8*half;
            int grow = i0 + lrow;
            float isv = sIs[lrow];
#pragma unroll
            for (int nt = 0; nt < NT; nt++) {
                float v0 = acc[mt][nt][half*2+0] * isv;
                float v1 = acc[mt][nt][half*2+1] * isv;
                if (LAYER == 1) {
                    v0 = v0 > 0.f ? v0 : expm1f(v0);
                    v1 = v1 > 0.f ? v1 : expm1f(v1);
                    float* o = d_hcat + ((long long)(b*NN + grow))*(NHEADS*NHID) + h*NHID + nt*8 + t*2;
                    *(float2*)o = make_float2(v0, v1);
                } else {
                    float* o = dout + ((long long)(b*NN + grow))*NCLASS + nt*8 + t*2;
                    *(float2*)o = make_float2(v0, v1);
                }
            }
        }
    }
}

// ---------------- 5) Wh2T = (hcat @ W_out)^T;  f2,g2 ----------------
// grid BB*NN/32, block 128
__global__ void whx2_kernel(const float* __restrict__ Wo,
                            const float* __restrict__ ao) {
    __shared__ float sH[32][257];
    __shared__ float sA[2*NCLASS];
    __shared__ float sRed[32][4][2];
    int r0 = blockIdx.x * 32;
    int tid = threadIdx.x;
    int r = tid & 31, ct = tid >> 5, c0 = ct*8;
    if (tid < 2*NCLASS) sA[tid] = ao[tid];
    for (int idx = tid; idx < 32*256/4; idx += 128) {
        int rr = idx >> 6, c4 = idx & 63;
        float4 v = *(const float4*)(&d_hcat[(long long)(r0+rr)*256 + c4*4]);
        sH[rr][c4*4+0]=v.x; sH[rr][c4*4+1]=v.y; sH[rr][c4*4+2]=v.z; sH[rr][c4*4+3]=v.w;
    }
    __syncthreads();
    float acc[8];
#pragma unroll
    for (int c = 0; c < 8; c++) acc[c] = 0.f;
#pragma unroll 4
    for (int k = 0; k < 256; k++) {
        float hv = sH[r][k];
        float4 w0 = __ldg((const float4*)(Wo + k*NCLASS + c0));
        float4 w1 = __ldg((const float4*)(Wo + k*NCLASS + c0 + 4));
        acc[0]+=hv*w0.x; acc[1]+=hv*w0.y; acc[2]+=hv*w0.z; acc[3]+=hv*w0.w;
        acc[4]+=hv*w1.x; acc[5]+=hv*w1.y; acc[6]+=hv*w1.z; acc[7]+=hv*w1.w;
    }
    int b = r0 >> 10;
    int j = (r0 & 1023) + r;
#pragma unroll
    for (int c = 0; c < 8; c++)
        d_Wh2T[((long long)b*NCLASS + c0 + c)*NN + j] = to_tf32(acc[c]);
    float pf = 0.f, pg = 0.f;
#pragma unroll
    for (int c = 0; c < 8; c++) { pf += acc[c]*sA[c0+c]; pg += acc[c]*sA[NCLASS+c0+c]; }
    sRed[r][ct][0] = pf; sRed[r][ct][1] = pg;
    __syncthreads();
    if (tid < 32) {
        float f = sRed[tid][0][0]+sRed[tid][1][0]+sRed[tid][2][0]+sRed[tid][3][0];
        float g = sRed[tid][0][1]+sRed[tid][1][1]+sRed[tid][2][1]+sRed[tid][3][1];
        d_f2[r0+tid] = f; d_g2[r0+tid] = g;
    }
}

// ---------------- 6) layer-2 softmax stats ----------------
__global__ void stats2_kernel() {
    __shared__ float sG[NN];
    int tid = threadIdx.x;
    int warp = tid >> 5, lane = tid & 31;
    int rowg = blockIdx.x*8 + warp;
    int b = rowg >> 10;
    for (int idx = tid; idx < NN; idx += 256) sG[idx] = d_g2[b*NN + idx];
    __syncthreads();
    unsigned word = d_adjR[rowg*32 + lane];
    float fv = d_f2[rowg];
    float mg = -1e30f;
#pragma unroll 4
    for (int w = 0; w < 32; w++) {
        unsigned ww = __shfl_sync(FULL, word, w);
        if ((ww >> lane) & 1u) mg = fmaxf(mg, sG[w*32 + lane]);
    }
#pragma unroll
    for (int off = 16; off > 0; off >>= 1)
        mg = fmaxf(mg, __shfl_xor_sync(FULL, mg, off));
    float xm = fv + mg;
    float m = xm > 0.f ? xm : LRA*xm;
    float s = 0.f;
#pragma unroll 4
    for (int w = 0; w < 32; w++) {
        unsigned ww = __shfl_sync(FULL, word, w);
        if ((ww >> lane) & 1u) {
            float xx = fv + sG[w*32 + lane];
            float e = xx > 0.f ? xx : LRA*xx;
            s += __expf(e - m);
        }
    }
#pragma unroll
    for (int off = 16; off > 0; off >>= 1)
        s += __shfl_xor_sync(FULL, s, off);
    if (lane == 0) {
        int i = rowg & 1023;
        d_is2[rowg] = 1.0f/fmaxf(s, 1e-30f);
        d_eac2[rowg] = make_float2(__expf(fv - m), __expf(LRA*fv - m));
        float gg = sG[i];
        d_gv2[rowg] = make_float4(gg, __expf(gg), __expf(LRA*gg), 0.f);
    }
}

// ---------------- launch ----------------
extern "C" void kernel_launch(void* const* d_in, const int* in_sizes, int n_in,
                              void* d_out, int out_size) {
    (void)in_sizes; (void)n_in; (void)out_size;
    const float* x       = (const float*)d_in[0];
    const int*   adj     = (const int*)  d_in[1];
    const float* W_heads = (const float*)d_in[2];
    const float* a_heads = (const float*)d_in[3];
    const float* W_out   = (const float*)d_in[4];
    const float* a_out   = (const float*)d_in[5];
    float* out = (float*)d_out;

    pack_adj_kernel<<<BB*NN/8, 256>>>(adj);
    whx1_kernel<<<dim3(NN/64, BB, NHEADS), 256>>>(x, W_heads, a_heads);
    stats1_kernel<<<BB*NN/8, 256>>>();
    pv_mma_kernel<1><<<dim3(NN/128, BB, NHEADS), 128>>>(nullptr);
    whx2_kernel<<<BB*NN/32, 128>>>(W_out, a_out);
    stats2_kernel<<<BB*NN/8, 256>>>();
    pv_mma_kernel<2><<<dim3(NN/128, BB, 1), 128>>>(out);
}